// round 6
// baseline (speedup 1.0000x reference)
#include <cuda_runtime.h>

#define NNODE 10000
#define NEDGE 320000
#define DDIM  256
#define TDIM  768     // 3*D
#define NLAYER 5

// ---------------- scratch (device globals; resolved ONLY inside device code) ----------------
__device__ float g_m[NNODE * DDIM];      // h @ W[l]
__device__ float g_agg[NNODE * DDIM];    // segment-sum result
__device__ float g_h[NNODE * DDIM];      // current hidden state
__device__ float g_gi[NNODE * TDIM];     // agg @ w_ih^T
__device__ float g_gh[NNODE * TDIM];     // h   @ w_hh^T
__device__ int   g_rowptr[NNODE + 1];
__device__ int   g_pos[NNODE];
__device__ int   g_csr_src[NEDGE];
__device__ float g_csr_w[NEDGE];

#define BUF_M   0
#define BUF_AGG 1
#define BUF_H   2
#define BUF_GI  3
#define BUF_GH  4

__device__ __forceinline__ float* buf_ptr(int id) {
    switch (id) {
        case BUF_M:   return g_m;
        case BUF_AGG: return g_agg;
        case BUF_H:   return g_h;
        case BUF_GI:  return g_gi;
        default:      return g_gh;
    }
}

// ---------------- CSR build ----------------
__global__ void k_zero_rowptr() {
    int i = blockIdx.x * blockDim.x + threadIdx.x;
    if (i <= NNODE) g_rowptr[i] = 0;
}

// edge_index is INT32 (JAX silently downcasts int64 without x64 mode):
// ei[0..E) = src, ei[E..2E) = dst.
__global__ void k_count(const int* __restrict__ ei) {
    int e = blockIdx.x * blockDim.x + threadIdx.x;
    if (e < NEDGE) {
        int d = ei[NEDGE + e];
        if (d >= 0 && d < NNODE) atomicAdd(&g_rowptr[d + 1], 1);
    }
}

// single-block inclusive scan over rowptr[0..N]; also seeds g_pos with row starts.
// rowptr after k_count holds deg[d] at index d+1 and 0 at index 0, so the
// inclusive scan at index i == sum(deg[0..i-1]) == row START of node i.
__global__ void k_scan() {
    __shared__ int s[1024];
    int tid = threadIdx.x;
    int carry = 0;
    for (int base = 0; base < NNODE + 1; base += 1024) {
        int i = base + tid;
        int v = (i < NNODE + 1) ? g_rowptr[i] : 0;
        __syncthreads();
        s[tid] = v;
        __syncthreads();
        for (int off = 1; off < 1024; off <<= 1) {
            int t = (tid >= off) ? s[tid - off] : 0;
            __syncthreads();
            s[tid] += t;
            __syncthreads();
        }
        int incl = s[tid] + carry;
        if (i < NNODE + 1) {
            g_rowptr[i] = incl;
            if (i < NNODE) g_pos[i] = incl;
        }
        carry += s[1023];
        __syncthreads();
    }
}

__global__ void k_fill(const int* __restrict__ ei, const float* __restrict__ attr) {
    int e = blockIdx.x * blockDim.x + threadIdx.x;
    if (e < NEDGE) {
        int d = ei[NEDGE + e];
        if (d >= 0 && d < NNODE) {
            int p = atomicAdd(&g_pos[d], 1);
            g_csr_src[p] = ei[e];
            g_csr_w[p]   = attr[e];
        }
    }
}

__global__ void k_copy_h(const float* __restrict__ x) {
    int i = blockIdx.x * blockDim.x + threadIdx.x;
    if (i < NNODE * DDIM) g_h[i] = x[i];
}

// ---------------- edge aggregation: one warp per destination node ----------------
__global__ void k_agg() {
    int w = (blockIdx.x * blockDim.x + threadIdx.x) >> 5;
    int lane = threadIdx.x & 31;
    if (w >= NNODE) return;
    int s0 = g_rowptr[w], s1 = g_rowptr[w + 1];
    float4 a0 = make_float4(0.f, 0.f, 0.f, 0.f);
    float4 a1 = a0;
    for (int e = s0; e < s1; ++e) {
        int   src = g_csr_src[e];
        float wt  = g_csr_w[e];
        const float4* row = (const float4*)(g_m + (size_t)src * DDIM);
        float4 v0 = row[lane];
        float4 v1 = row[lane + 32];
        a0.x += wt * v0.x; a0.y += wt * v0.y; a0.z += wt * v0.z; a0.w += wt * v0.w;
        a1.x += wt * v1.x; a1.y += wt * v1.y; a1.z += wt * v1.z; a1.w += wt * v1.w;
    }
    float4* o = (float4*)(g_agg + (size_t)w * DDIM);
    o[lane]      = a0;
    o[lane + 32] = a1;
}

// ---------------- SGEMM: C[M,Nc] = A[M,256] * op(B), fp32 ----------------
// TRANSB=false: B is [256, Nc] row-major (C = A*B)
// TRANSB=true : B is [Nc, 256] row-major (C = A*B^T)
template <bool TRANSB>
__global__ __launch_bounds__(256, 2) void k_sgemm(int aid,
                                                  const float* __restrict__ B,
                                                  int cid,
                                                  int M, int Nc) {
    const int K = 256, BM = 128, BN = 128, BK = 16;
    const int LDA = BM + 4, LDB = BN + 4;
    __shared__ float As[BK * LDA];
    __shared__ float Bs[BK * LDB];

    const float* __restrict__ A = buf_ptr(aid);
    float* __restrict__ C = buf_ptr(cid);

    int tid = threadIdx.x;
    int cx = tid & 15;        // column group 0..15
    int cy = tid >> 4;        // row group 0..15
    int mbase = blockIdx.y * BM;
    int nbase = blockIdx.x * BN;

    float acc[8][8];
#pragma unroll
    for (int i = 0; i < 8; ++i)
#pragma unroll
        for (int j = 0; j < 8; ++j) acc[i][j] = 0.f;

    for (int k0 = 0; k0 < K; k0 += BK) {
        // ---- load A tile (128 x 16), transposed into As[k][m]
#pragma unroll
        for (int t = 0; t < 2; ++t) {
            int L = tid + t * 256;
            int row = L >> 2, kv = L & 3;
            float4 v = make_float4(0.f, 0.f, 0.f, 0.f);
            int gr = mbase + row;
            if (gr < M) v = *(const float4*)(A + (size_t)gr * K + k0 + kv * 4);
            As[(kv * 4 + 0) * LDA + row] = v.x;
            As[(kv * 4 + 1) * LDA + row] = v.y;
            As[(kv * 4 + 2) * LDA + row] = v.z;
            As[(kv * 4 + 3) * LDA + row] = v.w;
        }
        // ---- load B tile into Bs[k][n]
        if (TRANSB) {
#pragma unroll
            for (int t = 0; t < 2; ++t) {
                int L = tid + t * 256;
                int row = L >> 2, kv = L & 3;   // row = n index (Nc multiple of 128)
                float4 v = *(const float4*)(B + (size_t)(nbase + row) * K + k0 + kv * 4);
                Bs[(kv * 4 + 0) * LDB + row] = v.x;
                Bs[(kv * 4 + 1) * LDB + row] = v.y;
                Bs[(kv * 4 + 2) * LDB + row] = v.z;
                Bs[(kv * 4 + 3) * LDB + row] = v.w;
            }
        } else {
#pragma unroll
            for (int t = 0; t < 2; ++t) {
                int L = tid + t * 256;
                int r = L >> 5, cv = L & 31;
                float4 v = *(const float4*)(B + (size_t)(k0 + r) * Nc + nbase + cv * 4);
                *(float4*)(Bs + r * LDB + cv * 4) = v;
            }
        }
        __syncthreads();

#pragma unroll
        for (int kk = 0; kk < BK; ++kk) {
            float4 a0 = *(float4*)(As + kk * LDA + cy * 4);
            float4 a1 = *(float4*)(As + kk * LDA + 64 + cy * 4);
            float4 b0 = *(float4*)(Bs + kk * LDB + cx * 4);
            float4 b1 = *(float4*)(Bs + kk * LDB + 64 + cx * 4);
            float a[8] = {a0.x, a0.y, a0.z, a0.w, a1.x, a1.y, a1.z, a1.w};
            float b[8] = {b0.x, b0.y, b0.z, b0.w, b1.x, b1.y, b1.z, b1.w};
#pragma unroll
            for (int i = 0; i < 8; ++i)
#pragma unroll
                for (int j = 0; j < 8; ++j) acc[i][j] += a[i] * b[j];
        }
        __syncthreads();
    }

#pragma unroll
    for (int i = 0; i < 8; ++i) {
        int lr = (i < 4) ? (cy * 4 + i) : (64 + cy * 4 + (i - 4));
        int gr = mbase + lr;
        if (gr < M) {
            *(float4*)(C + (size_t)gr * Nc + nbase + cx * 4) =
                make_float4(acc[i][0], acc[i][1], acc[i][2], acc[i][3]);
            *(float4*)(C + (size_t)gr * Nc + nbase + 64 + cx * 4) =
                make_float4(acc[i][4], acc[i][5], acc[i][6], acc[i][7]);
        }
    }
}

// ---------------- GRU elementwise ----------------
__global__ void k_gru(const float* __restrict__ bih, const float* __restrict__ bhh,
                      float* __restrict__ out, int use_out) {
    int i = blockIdx.x * blockDim.x + threadIdx.x;
    if (i >= NNODE * DDIM) return;
    int n = i >> 8, d = i & 255;
    const float* gi = g_gi + (size_t)n * TDIM;
    const float* gh = g_gh + (size_t)n * TDIM;
    float ir  = gi[d]       + bih[d];
    float iz  = gi[256 + d] + bih[256 + d];
    float in_ = gi[512 + d] + bih[512 + d];
    float hr  = gh[d]       + bhh[d];
    float hz  = gh[256 + d] + bhh[256 + d];
    float hn  = gh[512 + d] + bhh[512 + d];
    float r = 1.f / (1.f + expf(-(ir + hr)));
    float z = 1.f / (1.f + expf(-(iz + hz)));
    float nv = tanhf(in_ + r * hn);
    float hprev = g_h[i];
    float res = (1.f - z) * nv + z * hprev;
    if (use_out) out[i] = res;
    else         g_h[i] = res;
}

// ---------------- launch ----------------
extern "C" void kernel_launch(void* const* d_in, const int* in_sizes, int n_in,
                              void* d_out, int out_size) {
    const float* x      = (const float*)d_in[0];
    const int*   ei     = (const int*)d_in[1];      // int32! (JAX x64 disabled)
    const float* attr   = (const float*)d_in[2];
    const float* weight = (const float*)d_in[3];
    const float* w_ih   = (const float*)d_in[4];
    const float* w_hh   = (const float*)d_in[5];
    const float* b_ih   = (const float*)d_in[6];
    const float* b_hh   = (const float*)d_in[7];
    float* out = (float*)d_out;

    // CSR build (once per launch)
    k_zero_rowptr<<<(NNODE + 256) / 256, 256>>>();
    k_count<<<(NEDGE + 255) / 256, 256>>>(ei);
    k_scan<<<1, 1024>>>();
    k_fill<<<(NEDGE + 255) / 256, 256>>>(ei, attr);
    k_copy_h<<<(NNODE * DDIM + 1023) / 1024, 1024>>>(x);

    dim3 g1(DDIM / 128, (NNODE + 127) / 128);   // (2, 79)
    dim3 g3(TDIM / 128, (NNODE + 127) / 128);   // (6, 79)

    for (int l = 0; l < NLAYER; ++l) {
        k_sgemm<false><<<g1, 256>>>(BUF_H, weight + (size_t)l * DDIM * DDIM, BUF_M, NNODE, DDIM);
        k_agg<<<(NNODE * 32 + 255) / 256, 256>>>();
        k_sgemm<true><<<g3, 256>>>(BUF_AGG, w_ih, BUF_GI, NNODE, TDIM);
        k_sgemm<true><<<g3, 256>>>(BUF_H,   w_hh, BUF_GH, NNODE, TDIM);
        int last = (l == NLAYER - 1) ? 1 : 0;
        k_gru<<<(NNODE * DDIM + 255) / 256, 256>>>(b_ih, b_hh, out, last);
    }
}

// round 10
// speedup vs baseline: 1.7825x; 1.7825x over previous
#include <cuda_runtime.h>
#include <cuda_bf16.h>
#include <cstdint>

#define NNODE 10000
#define NPAD  10112           // 79*128
#define NEDGE 320000
#define DDIM  256
#define TDIM  768             // 3*D
#define NLAYER 5

// ================= device scratch (never passed as kernel params) =================
__device__ float g_m[NNODE * DDIM];          // h @ W[l]  (fp32)
__device__ float g_h[NNODE * DDIM];          // hidden state fp32
__device__ float g_gi[NNODE * TDIM];
__device__ float g_gh[NNODE * TDIM];
__device__ __nv_bfloat16 g_h_hi[NPAD * DDIM], g_h_lo[NPAD * DDIM];
__device__ __nv_bfloat16 g_agg_hi[NPAD * DDIM], g_agg_lo[NPAD * DDIM];
__device__ __nv_bfloat16 g_wt_hi[NLAYER * DDIM * DDIM], g_wt_lo[NLAYER * DDIM * DDIM]; // W^T
__device__ __nv_bfloat16 g_wih_hi[TDIM * DDIM], g_wih_lo[TDIM * DDIM];
__device__ __nv_bfloat16 g_whh_hi[TDIM * DDIM], g_whh_lo[TDIM * DDIM];
__device__ int   g_rowptr[NNODE + 1];
__device__ int   g_pos[NNODE];
__device__ int   g_csr_src[NEDGE];
__device__ float g_csr_w[NEDGE];

// ================= helpers =================
__device__ __forceinline__ uint32_t smem_u32(const void* p) {
    uint32_t a;
    asm("{ .reg .u64 t; cvta.to.shared.u64 t, %1; cvt.u32.u64 %0, t; }" : "=r"(a) : "l"(p));
    return a;
}
__device__ __forceinline__ void f2bf2(float v, __nv_bfloat16& hi, __nv_bfloat16& lo) {
    hi = __float2bfloat16_rn(v);
    lo = __float2bfloat16_rn(v - __bfloat162float(hi));
}

#define LDSM4(r, addr) \
    asm volatile("ldmatrix.sync.aligned.m8n8.x4.shared.b16 {%0,%1,%2,%3}, [%4];" \
        : "=r"((r)[0]), "=r"((r)[1]), "=r"((r)[2]), "=r"((r)[3]) : "r"(addr))

#define MMA16816(c, a, b0, b1) \
    asm volatile("mma.sync.aligned.m16n8k16.row.col.f32.bf16.bf16.f32 " \
        "{%0,%1,%2,%3}, {%4,%5,%6,%7}, {%8,%9}, {%0,%1,%2,%3};" \
        : "+f"((c)[0]), "+f"((c)[1]), "+f"((c)[2]), "+f"((c)[3]) \
        : "r"((a)[0]), "r"((a)[1]), "r"((a)[2]), "r"((a)[3]), "r"(b0), "r"(b1))

#define CP_ASYNC16(saddr, gptr) \
    asm volatile("cp.async.ca.shared.global [%0], [%1], 16;" :: "r"(saddr), "l"(gptr))
#define CP_COMMIT() asm volatile("cp.async.commit_group;" ::: "memory")
#define CP_WAIT1()  asm volatile("cp.async.wait_group 1;" ::: "memory")

// ================= CSR build =================
__global__ void k_zero_rowptr() {
    int i = blockIdx.x * blockDim.x + threadIdx.x;
    if (i <= NNODE) g_rowptr[i] = 0;
}
__global__ void k_count(const int* __restrict__ ei) {
    int e = blockIdx.x * blockDim.x + threadIdx.x;
    if (e < NEDGE) {
        int d = ei[NEDGE + e];
        if (d >= 0 && d < NNODE) atomicAdd(&g_rowptr[d + 1], 1);
    }
}
__global__ void k_scan() {
    __shared__ int s[1024];
    int tid = threadIdx.x;
    int carry = 0;
    for (int base = 0; base < NNODE + 1; base += 1024) {
        int i = base + tid;
        int v = (i < NNODE + 1) ? g_rowptr[i] : 0;
        __syncthreads();
        s[tid] = v;
        __syncthreads();
        for (int off = 1; off < 1024; off <<= 1) {
            int t = (tid >= off) ? s[tid - off] : 0;
            __syncthreads();
            s[tid] += t;
            __syncthreads();
        }
        int incl = s[tid] + carry;
        if (i < NNODE + 1) {
            g_rowptr[i] = incl;
            if (i < NNODE) g_pos[i] = incl;
        }
        carry += s[1023];
        __syncthreads();
    }
}
__global__ void k_fill(const int* __restrict__ ei, const float* __restrict__ attr) {
    int e = blockIdx.x * blockDim.x + threadIdx.x;
    if (e < NEDGE) {
        int d = ei[NEDGE + e];
        if (d >= 0 && d < NNODE) {
            int p = atomicAdd(&g_pos[d], 1);
            g_csr_src[p] = ei[e];
            g_csr_w[p]   = attr[e];
        }
    }
}

// ================= one-time conversions =================
__global__ void k_zero_pads() {
    int i = blockIdx.x * blockDim.x + threadIdx.x;
    int npad = (NPAD - NNODE) * DDIM;
    if (i < npad) {
        __nv_bfloat16 z = __float2bfloat16(0.f);
        g_h_hi[NNODE * DDIM + i] = z;  g_h_lo[NNODE * DDIM + i] = z;
        g_agg_hi[NNODE * DDIM + i] = z; g_agg_lo[NNODE * DDIM + i] = z;
    }
}
__global__ void k_conv_w(const float* __restrict__ weight,
                         const float* __restrict__ wih,
                         const float* __restrict__ whh) {
    int i = blockIdx.x * blockDim.x + threadIdx.x;
    if (i < NLAYER * DDIM * DDIM) {
        int l = i >> 16, r = i & 65535, k = r >> 8, j = r & 255;
        __nv_bfloat16 hi, lo;
        f2bf2(weight[i], hi, lo);
        int o = (l << 16) + j * DDIM + k;   // transpose to [j][k]
        g_wt_hi[o] = hi; g_wt_lo[o] = lo;
    }
    if (i < TDIM * DDIM) {
        __nv_bfloat16 hi, lo;
        f2bf2(wih[i], hi, lo); g_wih_hi[i] = hi; g_wih_lo[i] = lo;
        f2bf2(whh[i], hi, lo); g_whh_hi[i] = hi; g_whh_lo[i] = lo;
    }
}
__global__ void k_conv_x(const float* __restrict__ x) {
    int i = blockIdx.x * blockDim.x + threadIdx.x;
    if (i < NNODE * DDIM) {
        float v = x[i];
        g_h[i] = v;
        __nv_bfloat16 hi, lo;
        f2bf2(v, hi, lo);
        g_h_hi[i] = hi; g_h_lo[i] = lo;
    }
}

// ================= aggregation: one warp per node; emits bf16 pairs =================
__global__ void k_agg() {
    int w = (blockIdx.x * blockDim.x + threadIdx.x) >> 5;
    int lane = threadIdx.x & 31;
    if (w >= NNODE) return;
    int s0 = g_rowptr[w], s1 = g_rowptr[w + 1];
    float4 a0 = make_float4(0.f, 0.f, 0.f, 0.f);
    float4 a1 = a0;
    for (int e = s0; e < s1; ++e) {
        int   src = g_csr_src[e];
        float wt  = g_csr_w[e];
        const float4* row = (const float4*)(g_m + (size_t)src * DDIM);
        float4 v0 = row[lane];
        float4 v1 = row[lane + 32];
        a0.x += wt * v0.x; a0.y += wt * v0.y; a0.z += wt * v0.z; a0.w += wt * v0.w;
        a1.x += wt * v1.x; a1.y += wt * v1.y; a1.z += wt * v1.z; a1.w += wt * v1.w;
    }
    int b0 = w * DDIM + lane * 4;
    int b1 = w * DDIM + 128 + lane * 4;
    float v[8] = {a0.x, a0.y, a0.z, a0.w, a1.x, a1.y, a1.z, a1.w};
#pragma unroll
    for (int q = 0; q < 4; ++q) {
        __nv_bfloat16 hi, lo;
        f2bf2(v[q], hi, lo);
        g_agg_hi[b0 + q] = hi; g_agg_lo[b0 + q] = lo;
        f2bf2(v[4 + q], hi, lo);
        g_agg_hi[b1 + q] = hi; g_agg_lo[b1 + q] = lo;
    }
}

// ================= mma.sync bf16-split GEMM =================
// C[M,*] fp32 = Ahi*Bhi^T + Ahi*Blo^T + Alo*Bhi^T
// CTA: 128x128 tile, K=256, BK=32, 8 warps (2x4), warp tile 64x32.
// SMEM rows: 32 halves used, stride 40 halves (80 B) -> conflict-free ldmatrix.
#define LDSB   80            // bytes per smem row
#define S_AHI  0
#define S_ALO  10240
#define S_BHI  20480
#define S_BLO  30720
#define STAGE  40960
#define SMEM_GEMM (2 * STAGE)

__device__ __forceinline__ void gemm_prefetch(uint32_t sb, int st, int k0,
                                              const __nv_bfloat16* Ahi, const __nv_bfloat16* Alo,
                                              const __nv_bfloat16* Bhi, const __nv_bfloat16* Blo,
                                              int mbase, int nbase) {
    int t = threadIdx.x;
    uint32_t stb = sb + st * STAGE;
#pragma unroll
    for (int c = 0; c < 2; ++c) {
        int chunk = t * 2 + c;
        int row = chunk >> 2, kc = chunk & 3;
        uint32_t so = row * LDSB + kc * 16;
        size_t ga = (size_t)(mbase + row) * DDIM + k0 + kc * 8;
        size_t gb = (size_t)(nbase + row) * DDIM + k0 + kc * 8;
        CP_ASYNC16(stb + S_AHI + so, Ahi + ga);
        CP_ASYNC16(stb + S_ALO + so, Alo + ga);
        CP_ASYNC16(stb + S_BHI + so, Bhi + gb);
        CP_ASYNC16(stb + S_BLO + so, Blo + gb);
    }
}

__global__ __launch_bounds__(256, 1)
void k_mma_gemm(int base_id, int layer) {
    extern __shared__ char smem[];
    uint32_t sb = smem_u32(smem);
    int tid = threadIdx.x, wid = tid >> 5, lane = tid & 31;
    int wm = wid >> 2, wn = wid & 3;                 // 2 x 4 warp grid
    int m_off = wm * 64, n_off = wn * 32;
    int gemm_id = base_id + blockIdx.z;
    int mbase = blockIdx.y * 128;
    int nbase = blockIdx.x * 128;

    const __nv_bfloat16 *Ahi, *Alo, *Bhi, *Blo;
    float* Cp; int ldc;
    switch (gemm_id) {
        case 0:  Ahi = g_h_hi;   Alo = g_h_lo;
                 Bhi = g_wt_hi + (layer << 16); Blo = g_wt_lo + (layer << 16);
                 Cp = g_m;  ldc = DDIM; break;
        case 1:  Ahi = g_agg_hi; Alo = g_agg_lo;
                 Bhi = g_wih_hi; Blo = g_wih_lo;
                 Cp = g_gi; ldc = TDIM; break;
        default: Ahi = g_h_hi;   Alo = g_h_lo;
                 Bhi = g_whh_hi; Blo = g_whh_lo;
                 Cp = g_gh; ldc = TDIM; break;
    }

    float acc[4][4][4];
#pragma unroll
    for (int i = 0; i < 4; ++i)
#pragma unroll
        for (int j = 0; j < 4; ++j)
#pragma unroll
            for (int q = 0; q < 4; ++q) acc[i][j][q] = 0.f;

    gemm_prefetch(sb, 0, 0,  Ahi, Alo, Bhi, Blo, mbase, nbase); CP_COMMIT();
    gemm_prefetch(sb, 1, 32, Ahi, Alo, Bhi, Blo, mbase, nbase); CP_COMMIT();

    // precomputed ldmatrix lane offsets (bytes)
    uint32_t a_lane = (uint32_t)((lane & 15) * LDSB + (lane >> 4) * 16);
    uint32_t b_lane = (uint32_t)(((lane & 7) + ((lane >> 4) << 3)) * LDSB + (((lane >> 3) & 1) << 4));

    for (int it = 0; it < 8; ++it) {
        CP_WAIT1();
        __syncthreads();
        uint32_t stb = sb + (it & 1) * STAGE;
#pragma unroll
        for (int k16 = 0; k16 < 2; ++k16) {
            uint32_t kb = k16 * 32;   // 16 halves
            uint32_t a_hi[4][4], a_lo[4][4], b_hi[2][4], b_lo[2][4];
#pragma unroll
            for (int mi = 0; mi < 4; ++mi) {
                uint32_t ab = stb + (uint32_t)((m_off + mi * 16) * LDSB) + a_lane + kb;
                LDSM4(a_hi[mi], ab + S_AHI);
                LDSM4(a_lo[mi], ab + S_ALO);
            }
#pragma unroll
            for (int nb = 0; nb < 2; ++nb) {
                uint32_t bb = stb + (uint32_t)((n_off + nb * 16) * LDSB) + b_lane + kb;
                LDSM4(b_hi[nb], bb + S_BHI);
                LDSM4(b_lo[nb], bb + S_BLO);
            }
#pragma unroll
            for (int mi = 0; mi < 4; ++mi)
#pragma unroll
                for (int ni = 0; ni < 4; ++ni) {
                    int g = ni >> 1, p = (ni & 1) * 2;
                    MMA16816(acc[mi][ni], a_hi[mi], b_hi[g][p], b_hi[g][p + 1]);
                    MMA16816(acc[mi][ni], a_hi[mi], b_lo[g][p], b_lo[g][p + 1]);
                    MMA16816(acc[mi][ni], a_lo[mi], b_hi[g][p], b_hi[g][p + 1]);
                }
        }
        __syncthreads();
        if (it + 2 < 8)
            gemm_prefetch(sb, it & 1, (it + 2) * 32, Ahi, Alo, Bhi, Blo, mbase, nbase);
        CP_COMMIT();
    }

    // ---- epilogue: fragment (mi,ni): rows r, r+8; cols 2*(lane%4)+{0,1}
#pragma unroll
    for (int mi = 0; mi < 4; ++mi) {
#pragma unroll
        for (int ni = 0; ni < 4; ++ni) {
            int r  = mbase + m_off + mi * 16 + (lane >> 2);
            int cl = nbase + n_off + ni * 8 + (lane & 3) * 2;
            if (r < NNODE)
                *(float2*)(Cp + (size_t)r * ldc + cl) = make_float2(acc[mi][ni][0], acc[mi][ni][1]);
            if (r + 8 < NNODE)
                *(float2*)(Cp + (size_t)(r + 8) * ldc + cl) = make_float2(acc[mi][ni][2], acc[mi][ni][3]);
        }
    }
}

// ================= GRU elementwise (also emits next-layer bf16 pairs) =================
__global__ void k_gru(const float* __restrict__ bih, const float* __restrict__ bhh,
                      float* __restrict__ out, int use_out) {
    int i = blockIdx.x * blockDim.x + threadIdx.x;
    if (i >= NNODE * DDIM) return;
    int n = i >> 8, d = i & 255;
    const float* gi = g_gi + (size_t)n * TDIM;
    const float* gh = g_gh + (size_t)n * TDIM;
    float ir  = gi[d]       + bih[d];
    float iz  = gi[256 + d] + bih[256 + d];
    float in_ = gi[512 + d] + bih[512 + d];
    float hr  = gh[d]       + bhh[d];
    float hz  = gh[256 + d] + bhh[256 + d];
    float hn  = gh[512 + d] + bhh[512 + d];
    float r = 1.f / (1.f + expf(-(ir + hr)));
    float z = 1.f / (1.f + expf(-(iz + hz)));
    float nv = tanhf(in_ + r * hn);
    float res = (1.f - z) * nv + z * g_h[i];
    if (use_out) {
        out[i] = res;
    } else {
        g_h[i] = res;
        __nv_bfloat16 hi, lo;
        f2bf2(res, hi, lo);
        g_h_hi[i] = hi; g_h_lo[i] = lo;
    }
}

// ================= launch =================
extern "C" void kernel_launch(void* const* d_in, const int* in_sizes, int n_in,
                              void* d_out, int out_size) {
    const float* x      = (const float*)d_in[0];
    const int*   ei     = (const int*)d_in[1];      // int32 (JAX x64 disabled)
    const float* attr   = (const float*)d_in[2];
    const float* weight = (const float*)d_in[3];
    const float* w_ih   = (const float*)d_in[4];
    const float* w_hh   = (const float*)d_in[5];
    const float* b_ih   = (const float*)d_in[6];
    const float* b_hh   = (const float*)d_in[7];
    float* out = (float*)d_out;

    static bool attr_set = false;
    if (!attr_set) {
        cudaFuncSetAttribute(k_mma_gemm, cudaFuncAttributeMaxDynamicSharedMemorySize, SMEM_GEMM);
        attr_set = true;
    }

    // CSR + conversions (once per launch)
    k_zero_rowptr<<<(NNODE + 256) / 256, 256>>>();
    k_count<<<(NEDGE + 255) / 256, 256>>>(ei);
    k_scan<<<1, 1024>>>();
    k_fill<<<(NEDGE + 255) / 256, 256>>>(ei, attr);
    k_zero_pads<<<((NPAD - NNODE) * DDIM + 255) / 256, 256>>>();
    k_conv_w<<<(NLAYER * DDIM * DDIM + 255) / 256, 256>>>(weight, w_ih, w_hh);
    k_conv_x<<<(NNODE * DDIM + 255) / 256, 256>>>(x);

    dim3 gm_grid(DDIM / 128, NPAD / 128, 1);   // (2, 79, 1)
    dim3 gg_grid(TDIM / 128, NPAD / 128, 2);   // (6, 79, 2)

    for (int l = 0; l < NLAYER; ++l) {
        k_mma_gemm<<<gm_grid, 256, SMEM_GEMM>>>(0, l);
        k_agg<<<(NNODE * 32 + 255) / 256, 256>>>();
        k_mma_gemm<<<gg_grid, 256, SMEM_GEMM>>>(1, l);
        int last = (l == NLAYER - 1) ? 1 : 0;
        k_gru<<<(NNODE * DDIM + 255) / 256, 256>>>(b_ih, b_hh, out, last);
    }
}

// round 15
// speedup vs baseline: 2.0346x; 1.1414x over previous
#include <cuda_runtime.h>
#include <cuda_bf16.h>
#include <cstdint>

#define NNODE 10000
#define NPAD  10112           // 79*128
#define NEDGE 320000
#define DDIM  256
#define TDIM  768             // 3*D
#define NLAYER 5

// ================= device scratch (never passed as kernel params) =================
__device__ float g_h[NNODE * DDIM];          // hidden state fp32
__device__ float g_gi[NNODE * TDIM];
__device__ float g_gh[NNODE * TDIM];
__device__ float g_f[NLAYER * TDIM * DDIM];  // fused F[l] = w_ih * W[l]^T  (fp32)
__device__ __nv_bfloat16 g_h_hi[NPAD * DDIM], g_h_lo[NPAD * DDIM];
__device__ __nv_bfloat16 g_aggh_hi[NPAD * DDIM], g_aggh_lo[NPAD * DDIM];
__device__ __nv_bfloat16 g_w_hi[NLAYER * DDIM * DDIM], g_w_lo[NLAYER * DDIM * DDIM]; // W (untransposed)
__device__ __nv_bfloat16 g_wih_hi[TDIM * DDIM], g_wih_lo[TDIM * DDIM];
__device__ __nv_bfloat16 g_whh_hi[TDIM * DDIM], g_whh_lo[TDIM * DDIM];
__device__ __nv_bfloat16 g_f_hi[NLAYER * TDIM * DDIM], g_f_lo[NLAYER * TDIM * DDIM];
__device__ int   g_rowptr[NNODE + 1];
__device__ int   g_pos[NNODE];
__device__ int   g_csr_src[NEDGE];
__device__ float g_csr_w[NEDGE];

// ================= helpers =================
__device__ __forceinline__ uint32_t smem_u32(const void* p) {
    uint32_t a;
    asm("{ .reg .u64 t; cvta.to.shared.u64 t, %1; cvt.u32.u64 %0, t; }" : "=r"(a) : "l"(p));
    return a;
}
__device__ __forceinline__ void f2bf2(float v, __nv_bfloat16& hi, __nv_bfloat16& lo) {
    hi = __float2bfloat16_rn(v);
    lo = __float2bfloat16_rn(v - __bfloat162float(hi));
}

#define LDSM4(r, addr) \
    asm volatile("ldmatrix.sync.aligned.m8n8.x4.shared.b16 {%0,%1,%2,%3}, [%4];" \
        : "=r"((r)[0]), "=r"((r)[1]), "=r"((r)[2]), "=r"((r)[3]) : "r"(addr))

#define MMA16816(c, a, b0, b1) \
    asm volatile("mma.sync.aligned.m16n8k16.row.col.f32.bf16.bf16.f32 " \
        "{%0,%1,%2,%3}, {%4,%5,%6,%7}, {%8,%9}, {%0,%1,%2,%3};" \
        : "+f"((c)[0]), "+f"((c)[1]), "+f"((c)[2]), "+f"((c)[3]) \
        : "r"((a)[0]), "r"((a)[1]), "r"((a)[2]), "r"((a)[3]), "r"(b0), "r"(b1))

#define CP_ASYNC16(saddr, gptr) \
    asm volatile("cp.async.ca.shared.global [%0], [%1], 16;" :: "r"(saddr), "l"(gptr))
#define CP_COMMIT() asm volatile("cp.async.commit_group;" ::: "memory")
#define CP_WAIT1()  asm volatile("cp.async.wait_group 1;" ::: "memory")

// ================= CSR build =================
__global__ void k_zero_rowptr() {
    int i = blockIdx.x * blockDim.x + threadIdx.x;
    if (i <= NNODE) g_rowptr[i] = 0;
}
__global__ void k_count(const int* __restrict__ ei) {
    int e = blockIdx.x * blockDim.x + threadIdx.x;
    if (e < NEDGE) {
        int d = ei[NEDGE + e];
        if (d >= 0 && d < NNODE) atomicAdd(&g_rowptr[d + 1], 1);
    }
}
__global__ void k_scan() {
    __shared__ int s[1024];
    int tid = threadIdx.x;
    int carry = 0;
    for (int base = 0; base < NNODE + 1; base += 1024) {
        int i = base + tid;
        int v = (i < NNODE + 1) ? g_rowptr[i] : 0;
        __syncthreads();
        s[tid] = v;
        __syncthreads();
        for (int off = 1; off < 1024; off <<= 1) {
            int t = (tid >= off) ? s[tid - off] : 0;
            __syncthreads();
            s[tid] += t;
            __syncthreads();
        }
        int incl = s[tid] + carry;
        if (i < NNODE + 1) {
            g_rowptr[i] = incl;
            if (i < NNODE) g_pos[i] = incl;
        }
        carry += s[1023];
        __syncthreads();
    }
}
__global__ void k_fill(const int* __restrict__ ei, const float* __restrict__ attr) {
    int e = blockIdx.x * blockDim.x + threadIdx.x;
    if (e < NEDGE) {
        int d = ei[NEDGE + e];
        if (d >= 0 && d < NNODE) {
            int p = atomicAdd(&g_pos[d], 1);
            g_csr_src[p] = ei[e];
            g_csr_w[p]   = attr[e];
        }
    }
}

// ================= one-time conversions =================
__global__ void k_zero_pads() {
    int i = blockIdx.x * blockDim.x + threadIdx.x;
    int npad = (NPAD - NNODE) * DDIM;
    if (i < npad) {
        __nv_bfloat16 z = __float2bfloat16(0.f);
        g_h_hi[NNODE * DDIM + i] = z;    g_h_lo[NNODE * DDIM + i] = z;
        g_aggh_hi[NNODE * DDIM + i] = z; g_aggh_lo[NNODE * DDIM + i] = z;
    }
}
// W untransposed pairs; w_ih / w_hh elementwise pairs
__global__ void k_conv_w(const float* __restrict__ weight,
                         const float* __restrict__ wih,
                         const float* __restrict__ whh) {
    int i = blockIdx.x * blockDim.x + threadIdx.x;
    if (i < NLAYER * DDIM * DDIM) {
        __nv_bfloat16 hi, lo;
        f2bf2(weight[i], hi, lo);
        g_w_hi[i] = hi; g_w_lo[i] = lo;
    }
    if (i < TDIM * DDIM) {
        __nv_bfloat16 hi, lo;
        f2bf2(wih[i], hi, lo); g_wih_hi[i] = hi; g_wih_lo[i] = lo;
        f2bf2(whh[i], hi, lo); g_whh_hi[i] = hi; g_whh_lo[i] = lo;
    }
}
__global__ void k_conv_x(const float* __restrict__ x) {
    int i = blockIdx.x * blockDim.x + threadIdx.x;
    if (i < NNODE * DDIM) {
        float v = x[i];
        g_h[i] = v;
        __nv_bfloat16 hi, lo;
        f2bf2(v, hi, lo);
        g_h_hi[i] = hi; g_h_lo[i] = lo;
    }
}
__global__ void k_split_f() {
    int i = blockIdx.x * blockDim.x + threadIdx.x;
    if (i < NLAYER * TDIM * DDIM) {
        __nv_bfloat16 hi, lo;
        f2bf2(g_f[i], hi, lo);
        g_f_hi[i] = hi; g_f_lo[i] = lo;
    }
}

// ================= aggregation of h: one warp per node; emits bf16 pairs =================
__global__ void k_agg() {
    int w = (blockIdx.x * blockDim.x + threadIdx.x) >> 5;
    int lane = threadIdx.x & 31;
    if (w >= NNODE) return;
    int s0 = g_rowptr[w], s1 = g_rowptr[w + 1];
    float4 a0 = make_float4(0.f, 0.f, 0.f, 0.f);
    float4 a1 = a0;
    for (int e = s0; e < s1; ++e) {
        int   src = g_csr_src[e];
        float wt  = g_csr_w[e];
        const float4* row = (const float4*)(g_h + (size_t)src * DDIM);
        float4 v0 = row[lane];
        float4 v1 = row[lane + 32];
        a0.x += wt * v0.x; a0.y += wt * v0.y; a0.z += wt * v0.z; a0.w += wt * v0.w;
        a1.x += wt * v1.x; a1.y += wt * v1.y; a1.z += wt * v1.z; a1.w += wt * v1.w;
    }
    int b0 = w * DDIM + lane * 4;
    int b1 = w * DDIM + 128 + lane * 4;
    float v[8] = {a0.x, a0.y, a0.z, a0.w, a1.x, a1.y, a1.z, a1.w};
#pragma unroll
    for (int q = 0; q < 4; ++q) {
        __nv_bfloat16 hi, lo;
        f2bf2(v[q], hi, lo);
        g_aggh_hi[b0 + q] = hi; g_aggh_lo[b0 + q] = lo;
        f2bf2(v[4 + q], hi, lo);
        g_aggh_hi[b1 + q] = hi; g_aggh_lo[b1 + q] = lo;
    }
}

// ================= mma.sync bf16-split GEMM (C = A x B^T, 3-term) =================
// CTA: 128x128 tile, K=256, BK=32, 8 warps (2x4), warp tile 64x32.
// SMEM rows: 32 halves used, stride 40 halves (80 B) -> conflict-free ldmatrix.
// gemm_id: 1 = gi = aggh x F[l]^T ; 2 = gh = h x w_hh^T ; 3 = F[l] = wih x W[l]^T (z=layer)
#define LDSB   80
#define S_AHI  0
#define S_ALO  10240
#define S_BHI  20480
#define S_BLO  30720
#define STAGE  40960
#define SMEM_GEMM (2 * STAGE)

__device__ __forceinline__ void gemm_prefetch(uint32_t sb, int st, int k0,
                                              const __nv_bfloat16* Ahi, const __nv_bfloat16* Alo,
                                              const __nv_bfloat16* Bhi, const __nv_bfloat16* Blo,
                                              int mbase, int nbase) {
    int t = threadIdx.x;
    uint32_t stb = sb + st * STAGE;
#pragma unroll
    for (int c = 0; c < 2; ++c) {
        int chunk = t * 2 + c;
        int row = chunk >> 2, kc = chunk & 3;
        uint32_t so = row * LDSB + kc * 16;
        size_t ga = (size_t)(mbase + row) * DDIM + k0 + kc * 8;
        size_t gb = (size_t)(nbase + row) * DDIM + k0 + kc * 8;
        CP_ASYNC16(stb + S_AHI + so, Ahi + ga);
        CP_ASYNC16(stb + S_ALO + so, Alo + ga);
        CP_ASYNC16(stb + S_BHI + so, Bhi + gb);
        CP_ASYNC16(stb + S_BLO + so, Blo + gb);
    }
}

__global__ __launch_bounds__(256, 1)
void k_mma_gemm(int gemm_id, int layer) {
    extern __shared__ char smem[];
    uint32_t sb = smem_u32(smem);
    int tid = threadIdx.x, wid = tid >> 5, lane = tid & 31;
    int wm = wid >> 2, wn = wid & 3;
    int m_off = wm * 64, n_off = wn * 32;
    if (gemm_id == 3) layer = blockIdx.z;
    int mbase = blockIdx.y * 128;
    int nbase = blockIdx.x * 128;

    const __nv_bfloat16 *Ahi, *Alo, *Bhi, *Blo;
    float* Cp; int ldc;
    switch (gemm_id) {
        case 1:  Ahi = g_aggh_hi; Alo = g_aggh_lo;
                 Bhi = g_f_hi + (size_t)layer * TDIM * DDIM;
                 Blo = g_f_lo + (size_t)layer * TDIM * DDIM;
                 Cp = g_gi; ldc = TDIM; break;
        case 2:  Ahi = g_h_hi;   Alo = g_h_lo;
                 Bhi = g_whh_hi; Blo = g_whh_lo;
                 Cp = g_gh; ldc = TDIM; break;
        default: Ahi = g_wih_hi; Alo = g_wih_lo;
                 Bhi = g_w_hi + (layer << 16);
                 Blo = g_w_lo + (layer << 16);
                 Cp = g_f + (size_t)layer * TDIM * DDIM; ldc = DDIM; break;
    }

    float acc[4][4][4];
#pragma unroll
    for (int i = 0; i < 4; ++i)
#pragma unroll
        for (int j = 0; j < 4; ++j)
#pragma unroll
            for (int q = 0; q < 4; ++q) acc[i][j][q] = 0.f;

    gemm_prefetch(sb, 0, 0,  Ahi, Alo, Bhi, Blo, mbase, nbase); CP_COMMIT();
    gemm_prefetch(sb, 1, 32, Ahi, Alo, Bhi, Blo, mbase, nbase); CP_COMMIT();

    uint32_t a_lane = (uint32_t)((lane & 15) * LDSB + (lane >> 4) * 16);
    uint32_t b_lane = (uint32_t)(((lane & 7) + ((lane >> 4) << 3)) * LDSB + (((lane >> 3) & 1) << 4));

    for (int it = 0; it < 8; ++it) {
        CP_WAIT1();
        __syncthreads();
        uint32_t stb = sb + (it & 1) * STAGE;
#pragma unroll
        for (int k16 = 0; k16 < 2; ++k16) {
            uint32_t kb = k16 * 32;
            uint32_t a_hi[4][4], a_lo[4][4], b_hi[2][4], b_lo[2][4];
#pragma unroll
            for (int mi = 0; mi < 4; ++mi) {
                uint32_t ab = stb + (uint32_t)((m_off + mi * 16) * LDSB) + a_lane + kb;
                LDSM4(a_hi[mi], ab + S_AHI);
                LDSM4(a_lo[mi], ab + S_ALO);
            }
#pragma unroll
            for (int nb = 0; nb < 2; ++nb) {
                uint32_t bb = stb + (uint32_t)((n_off + nb * 16) * LDSB) + b_lane + kb;
                LDSM4(b_hi[nb], bb + S_BHI);
                LDSM4(b_lo[nb], bb + S_BLO);
            }
#pragma unroll
            for (int mi = 0; mi < 4; ++mi)
#pragma unroll
                for (int ni = 0; ni < 4; ++ni) {
                    int g = ni >> 1, p = (ni & 1) * 2;
                    MMA16816(acc[mi][ni], a_hi[mi], b_hi[g][p], b_hi[g][p + 1]);
                    MMA16816(acc[mi][ni], a_hi[mi], b_lo[g][p], b_lo[g][p + 1]);
                    MMA16816(acc[mi][ni], a_lo[mi], b_hi[g][p], b_hi[g][p + 1]);
                }
        }
        __syncthreads();
        if (it + 2 < 8)
            gemm_prefetch(sb, it & 1, (it + 2) * 32, Ahi, Alo, Bhi, Blo, mbase, nbase);
        CP_COMMIT();
    }

#pragma unroll
    for (int mi = 0; mi < 4; ++mi) {
#pragma unroll
        for (int ni = 0; ni < 4; ++ni) {
            int r  = mbase + m_off + mi * 16 + (lane >> 2);
            int cl = nbase + n_off + ni * 8 + (lane & 3) * 2;
            if (r < NNODE)
                *(float2*)(Cp + (size_t)r * ldc + cl) = make_float2(acc[mi][ni][0], acc[mi][ni][1]);
            if (r + 8 < NNODE)
                *(float2*)(Cp + (size_t)(r + 8) * ldc + cl) = make_float2(acc[mi][ni][2], acc[mi][ni][3]);
        }
    }
}

// ================= GRU elementwise (also emits next-layer bf16 pairs) =================
__global__ void k_gru(const float* __restrict__ bih, const float* __restrict__ bhh,
                      float* __restrict__ out, int use_out) {
    int i = blockIdx.x * blockDim.x + threadIdx.x;
    if (i >= NNODE * DDIM) return;
    int n = i >> 8, d = i & 255;
    const float* gi = g_gi + (size_t)n * TDIM;
    const float* gh = g_gh + (size_t)n * TDIM;
    float ir  = gi[d]       + bih[d];
    float iz  = gi[256 + d] + bih[256 + d];
    float in_ = gi[512 + d] + bih[512 + d];
    float hr  = gh[d]       + bhh[d];
    float hz  = gh[256 + d] + bhh[256 + d];
    float hn  = gh[512 + d] + bhh[512 + d];
    float r = 1.f / (1.f + expf(-(ir + hr)));
    float z = 1.f / (1.f + expf(-(iz + hz)));
    float nv = tanhf(in_ + r * hn);
    float res = (1.f - z) * nv + z * g_h[i];
    if (use_out) {
        out[i] = res;
    } else {
        g_h[i] = res;
        __nv_bfloat16 hi, lo;
        f2bf2(res, hi, lo);
        g_h_hi[i] = hi; g_h_lo[i] = lo;
    }
}

// ================= launch =================
extern "C" void kernel_launch(void* const* d_in, const int* in_sizes, int n_in,
                              void* d_out, int out_size) {
    const float* x      = (const float*)d_in[0];
    const int*   ei     = (const int*)d_in[1];      // int32 (JAX x64 disabled)
    const float* attr   = (const float*)d_in[2];
    const float* weight = (const float*)d_in[3];
    const float* w_ih   = (const float*)d_in[4];
    const float* w_hh   = (const float*)d_in[5];
    const float* b_ih   = (const float*)d_in[6];
    const float* b_hh   = (const float*)d_in[7];
    float* out = (float*)d_out;

    static cudaStream_t s2 = nullptr;
    static cudaEvent_t e_fork = nullptr, e_join = nullptr;
    static bool init_done = false;
    if (!init_done) {
        cudaFuncSetAttribute(k_mma_gemm, cudaFuncAttributeMaxDynamicSharedMemorySize, SMEM_GEMM);
        cudaStreamCreateWithFlags(&s2, cudaStreamNonBlocking);
        cudaEventCreateWithFlags(&e_fork, cudaEventDisableTiming);
        cudaEventCreateWithFlags(&e_join, cudaEventDisableTiming);
        init_done = true;
    }

    // ---- setup (once per launch): CSR, conversions, fused F[l] = wih x W[l]^T
    k_zero_rowptr<<<(NNODE + 256) / 256, 256>>>();
    k_count<<<(NEDGE + 255) / 256, 256>>>(ei);
    k_scan<<<1, 1024>>>();
    k_fill<<<(NEDGE + 255) / 256, 256>>>(ei, attr);
    k_zero_pads<<<((NPAD - NNODE) * DDIM + 255) / 256, 256>>>();
    k_conv_w<<<(NLAYER * DDIM * DDIM + 255) / 256, 256>>>(weight, w_ih, w_hh);
    k_conv_x<<<(NNODE * DDIM + 255) / 256, 256>>>(x);

    dim3 f_grid(DDIM / 128, TDIM / 128, NLAYER);   // (2, 6, 5)
    k_mma_gemm<<<f_grid, 256, SMEM_GEMM>>>(3, 0);
    k_split_f<<<(NLAYER * TDIM * DDIM + 255) / 256, 256>>>();

    dim3 gg(TDIM / 128, NPAD / 128, 1);            // (6, 79)

    for (int l = 0; l < NLAYER; ++l) {
        // fork: gh = h @ w_hh^T on s2, concurrent with aggregation + gi on main
        cudaEventRecord(e_fork, 0);
        cudaStreamWaitEvent(s2, e_fork, 0);
        k_mma_gemm<<<gg, 256, SMEM_GEMM, s2>>>(2, l);

        k_agg<<<(NNODE * 32 + 255) / 256, 256>>>();
        k_mma_gemm<<<gg, 256, SMEM_GEMM>>>(1, l);

        cudaEventRecord(e_join, s2);
        cudaStreamWaitEvent(0, e_join, 0);

        int last = (l == NLAYER - 1) ? 1 : 0;
        k_gru<<<(NNODE * DDIM + 255) / 256, 256>>>(b_ih, b_hh, out, last);
    }
}